// round 2
// baseline (speedup 1.0000x reference)
#include <cuda_runtime.h>
#include <math.h>

#define Bsz 8
#define Sq 2048
#define Dd 256
#define Hh 8

#define BM 64
#define BN 32
#define QSP 68   // Qs row stride (floats): mult of 4 for LDS.128 alignment
#define KSP 34   // Ks row stride: mult of 2 for LDS.64 alignment
#define PSP 33   // Ps row stride: conflict-free row sums

// Scratch (no cudaMalloc allowed): folded projection matrix + pre-projected E
__device__ float g_weff[Dd * Dd];
__device__ float g_e2[(size_t)Bsz * Sq * Dd];

// ---------------------------------------------------------------------------
// Kernel 1: W_eff[d][dp] = sum_h W_o[d][h*256 + dp]
// ---------------------------------------------------------------------------
__global__ void weff_kernel(const float* __restrict__ Wo) {
    int d  = blockIdx.x;
    int dp = threadIdx.x;
    float s = 0.f;
#pragma unroll
    for (int h = 0; h < Hh; h++)
        s += Wo[(size_t)d * (Dd * Hh) + h * Dd + dp];
    g_weff[d * Dd + dp] = s;
}

// ---------------------------------------------------------------------------
// Kernel 2: e2[m][n] = sum_k e[m][k] * W_eff[n][k]   (M=16384, N=256, K=256)
// 64x64 tile, BK=32, 256 threads, 4x4 microtile.
// ---------------------------------------------------------------------------
__global__ void e2_gemm_kernel(const float* __restrict__ E) {
    __shared__ float As[32][68];   // [k][m], padded
    __shared__ float Bs[32][68];   // [k][n], padded
    int tid = threadIdx.x;
    int m0 = blockIdx.x * 64;
    int n0 = blockIdx.y * 64;
    int ty = tid >> 4, tx = tid & 15;
    int lr = tid >> 5;      // 0..7
    int lc = tid & 31;      // 0..31

    float acc[4][4];
#pragma unroll
    for (int i = 0; i < 4; i++)
#pragma unroll
        for (int j = 0; j < 4; j++) acc[i][j] = 0.f;

    for (int k0 = 0; k0 < Dd; k0 += 32) {
#pragma unroll
        for (int i = 0; i < 8; i++) {
            int row = lr + i * 8;
            As[lc][row] = E[(size_t)(m0 + row) * Dd + k0 + lc];
            Bs[lc][row] = g_weff[(size_t)(n0 + row) * Dd + k0 + lc];
        }
        __syncthreads();
#pragma unroll
        for (int kk = 0; kk < 32; kk++) {
            float4 a = *(const float4*)&As[kk][ty * 4];
            float4 b = *(const float4*)&Bs[kk][tx * 4];
            float av[4] = {a.x, a.y, a.z, a.w};
            float bv[4] = {b.x, b.y, b.z, b.w};
#pragma unroll
            for (int i = 0; i < 4; i++)
#pragma unroll
                for (int j = 0; j < 4; j++) acc[i][j] += av[i] * bv[j];
        }
        __syncthreads();
    }
#pragma unroll
    for (int i = 0; i < 4; i++) {
        float4 v = make_float4(acc[i][0], acc[i][1], acc[i][2], acc[i][3]);
        *(float4*)&g_e2[(size_t)(m0 + ty * 4 + i) * Dd + n0 + tx * 4] = v;
    }
}

// ---------------------------------------------------------------------------
// Kernel 3: causal attention with clipped scores (no softmax max needed).
// One CTA = 64 q-rows of one batch. Streams 32-wide k-tiles.
//   out[b][q][c] = (1/(q+1)) * (1/denom[q]) * sum_k exp(clip(q.k/16)) * e2[b][k][c]
// ---------------------------------------------------------------------------
__global__ void attn_kernel(const float* __restrict__ P, float* __restrict__ Out) {
    extern __shared__ float sm[];
    float* Qs = sm;                      // [256][QSP]  d-major
    float* Ks = Qs + 256 * QSP;          // [256][KSP]  d-major
    float* Es = Ks + 256 * KSP;          // [32][256]   k-major
    float* Ps = Es + 32 * 256;           // [64][PSP]   probabilities
    float* Dn = Ps + 64 * PSP;           // [64]        denominators

    int g = blockIdx.x;                       // 0..255, heaviest diagonals first
    int m = (gridDim.x / Bsz - 1) - (g >> 3); // q-tile index, descending
    int b = g & (Bsz - 1);
    int tid = threadIdx.x;
    int q0 = m * BM;
    const float* pb = P + (size_t)b * (Sq + 1) * Dd;

    // Load Q tile (rows q0..q0+63, p shifted by +1) transposed to d-major.
#pragma unroll 4
    for (int r = 0; r < BM; r++)
        Qs[tid * QSP + r] = pb[(size_t)(q0 + r + 1) * Dd + tid];
    if (tid < BM) Dn[tid] = 0.f;

    float acc[64];
#pragma unroll
    for (int i = 0; i < 64; i++) acc[i] = 0.f;

    int w = tid >> 5, lane = tid & 31;   // phase B mapping: warp w -> rows w*8..+7
    int ty = tid >> 4, tx = tid & 15;    // phase A mapping: 4x2 microtile

    int kend = q0 + BM;
    for (int kb = 0; kb < kend; kb += BN) {
        __syncthreads();
        // Load K tile transposed to d-major, E2 tile k-major.
#pragma unroll 4
        for (int kr = 0; kr < BN; kr++)
            Ks[tid * KSP + kr] = pb[(size_t)(kb + kr) * Dd + tid];
        const float* e2b = g_e2 + ((size_t)b * Sq + kb) * Dd;
#pragma unroll 4
        for (int kr = 0; kr < BN; kr++)
            Es[kr * 256 + tid] = e2b[kr * Dd + tid];
        __syncthreads();

        // Phase A: S[64][32] = Q . K^T  (4x2 per thread, vectorized smem reads)
        float s[4][2];
#pragma unroll
        for (int i = 0; i < 4; i++) { s[i][0] = 0.f; s[i][1] = 0.f; }
#pragma unroll 8
        for (int d = 0; d < 256; d++) {
            float4 q = *(const float4*)&Qs[d * QSP + ty * 4];
            float2 k = *(const float2*)&Ks[d * KSP + tx * 2];
            s[0][0] += q.x * k.x; s[0][1] += q.x * k.y;
            s[1][0] += q.y * k.x; s[1][1] += q.y * k.y;
            s[2][0] += q.z * k.x; s[2][1] += q.z * k.y;
            s[3][0] += q.w * k.x; s[3][1] += q.w * k.y;
        }
        // scale, clip, causal mask, exp -> Ps
#pragma unroll
        for (int i = 0; i < 4; i++)
#pragma unroll
            for (int j = 0; j < 2; j++) {
                int qr = q0 + ty * 4 + i;
                int kc = kb + tx * 2 + j;
                float v = s[i][j] * 0.0625f;
                v = fminf(fmaxf(v, -10.f), 10.f);
                Ps[(ty * 4 + i) * PSP + tx * 2 + j] = (kc <= qr) ? __expf(v) : 0.f;
            }
        __syncthreads();

        // Row denominators (2 warps; overlaps with phase B of other warps)
        if (tid < BM) {
            float sum = 0.f;
#pragma unroll
            for (int kk = 0; kk < BN; kk++) sum += Ps[tid * PSP + kk];
            Dn[tid] += sum;
        }

        // Phase B: acc[64][256] += P[64][32] . E2[32][256]
#pragma unroll 2
        for (int kk = 0; kk < BN; kk++) {
            float pv[8];
#pragma unroll
            for (int i = 0; i < 8; i++) pv[i] = Ps[(w * 8 + i) * PSP + kk];
#pragma unroll
            for (int u = 0; u < 8; u++) {
                float ev = Es[kk * 256 + lane + 32 * u];
#pragma unroll
                for (int i = 0; i < 8; i++) acc[i * 8 + u] += pv[i] * ev;
            }
        }
    }
    __syncthreads();

    // Epilogue: divide by denom, apply 1/(q+1) row scale, store.
    float* ob = Out + ((size_t)b * Sq + q0) * Dd;
#pragma unroll
    for (int i = 0; i < 8; i++) {
        int r = w * 8 + i;
        float scale = 1.f / ((float)(q0 + r + 1) * Dn[r]);
#pragma unroll
        for (int u = 0; u < 8; u++)
            ob[(size_t)r * Dd + lane + 32 * u] = acc[i * 8 + u] * scale;
    }
}

// ---------------------------------------------------------------------------
extern "C" void kernel_launch(void* const* d_in, const int* in_sizes, int n_in,
                              void* d_out, int out_size) {
    const float* e  = (const float*)d_in[0];
    const float* p  = (const float*)d_in[1];
    const float* Wo = (const float*)d_in[2];
    float* out = (float*)d_out;

    size_t smem = (size_t)(256 * QSP + 256 * KSP + 32 * 256 + 64 * PSP + 64) * sizeof(float);
    cudaFuncSetAttribute(attn_kernel, cudaFuncAttributeMaxDynamicSharedMemorySize, (int)smem);

    weff_kernel<<<Dd, Dd>>>(Wo);
    e2_gemm_kernel<<<dim3((Bsz * Sq) / 64, Dd / 64), 256>>>(e);
    attn_kernel<<<Bsz * (Sq / BM), 256, smem>>>(p, out);
}

// round 4
// speedup vs baseline: 1.9814x; 1.9814x over previous
#include <cuda_runtime.h>
#include <cuda_bf16.h>

#define Bsz 8
#define Sq  2048
#define Dd  256

__device__ float g_weff[Dd * Dd];
__device__ unsigned short g_ph[(size_t)Bsz * (Sq + 1) * Dd];
__device__ unsigned short g_pl[(size_t)Bsz * (Sq + 1) * Dd];
__device__ unsigned short g_eth[(size_t)Bsz * Dd * Sq];   // [b][c][s] hi
__device__ unsigned short g_etl[(size_t)Bsz * Dd * Sq];   // [b][c][s] lo

__device__ __forceinline__ unsigned pack_bf16(float a, float b) {
    __nv_bfloat162 t = __floats2bfloat162_rn(a, b);
    return *(unsigned*)&t;
}
__device__ __forceinline__ void mma16816(float* d, const unsigned* a, unsigned b0, unsigned b1) {
    asm volatile("mma.sync.aligned.m16n8k16.row.col.f32.bf16.bf16.f32 "
        "{%0,%1,%2,%3}, {%4,%5,%6,%7}, {%8,%9}, {%0,%1,%2,%3};"
        : "+f"(d[0]), "+f"(d[1]), "+f"(d[2]), "+f"(d[3])
        : "r"(a[0]), "r"(a[1]), "r"(a[2]), "r"(a[3]), "r"(b0), "r"(b1));
}
__device__ __forceinline__ void ldsm4(unsigned* r, unsigned addr) {
    asm volatile("ldmatrix.sync.aligned.m8n8.x4.shared.b16 {%0,%1,%2,%3}, [%4];"
        : "=r"(r[0]), "=r"(r[1]), "=r"(r[2]), "=r"(r[3]) : "r"(addr));
}
__device__ __forceinline__ unsigned smem_u32(const void* p) {
    unsigned a;
    asm("{ .reg .u64 t; cvta.to.shared.u64 t, %1; cvt.u32.u64 %0, t; }" : "=r"(a) : "l"(p));
    return a;
}

// ---------------- kernel 1: W_eff fold ----------------
__global__ void weff_kernel(const float* __restrict__ Wo) {
    int d = blockIdx.x, dp = threadIdx.x;
    float s = 0.f;
#pragma unroll
    for (int h = 0; h < 8; h++) s += Wo[(size_t)d * (Dd * 8) + h * Dd + dp];
    g_weff[d * Dd + dp] = s;
}

// ---------------- kernel 2: p -> bf16 hi/lo ----------------
__global__ void pconv_kernel(const float* __restrict__ P) {
    size_t i = (size_t)blockIdx.x * 256 + threadIdx.x;
    float4 v = ((const float4*)P)[i];
    float hx = __bfloat162float(__float2bfloat16(v.x));
    float hy = __bfloat162float(__float2bfloat16(v.y));
    float hz = __bfloat162float(__float2bfloat16(v.z));
    float hw = __bfloat162float(__float2bfloat16(v.w));
    ((uint2*)g_ph)[i] = make_uint2(pack_bf16(hx, hy), pack_bf16(hz, hw));
    ((uint2*)g_pl)[i] = make_uint2(pack_bf16(v.x - hx, v.y - hy), pack_bf16(v.z - hz, v.w - hw));
}

// ---------------- kernel 3: e2t[b][c][s] = sum_k Weff[c][k]*e[b][s][k] ----------------
__global__ void e2t_gemm_kernel(const float* __restrict__ E) {
    __shared__ float As[32][68], Bs[32][68];
    int tid = threadIdx.x;
    int s0 = blockIdx.x * 64, c0 = blockIdx.y * 64;
    int ty = tid >> 4, tx = tid & 15, lr = tid >> 5, lc = tid & 31;
    float acc[4][4];
#pragma unroll
    for (int i = 0; i < 4; i++)
#pragma unroll
        for (int j = 0; j < 4; j++) acc[i][j] = 0.f;
    for (int k0 = 0; k0 < Dd; k0 += 32) {
#pragma unroll
        for (int i = 0; i < 8; i++) {
            int row = lr + i * 8;
            As[lc][row] = g_weff[(size_t)(c0 + row) * Dd + k0 + lc];
            Bs[lc][row] = E[(size_t)(s0 + row) * Dd + k0 + lc];
        }
        __syncthreads();
#pragma unroll
        for (int kk = 0; kk < 32; kk++) {
            float4 a = *(const float4*)&As[kk][ty * 4];
            float4 b = *(const float4*)&Bs[kk][tx * 4];
            float av[4] = {a.x, a.y, a.z, a.w}, bv[4] = {b.x, b.y, b.z, b.w};
#pragma unroll
            for (int i = 0; i < 4; i++)
#pragma unroll
                for (int j = 0; j < 4; j++) acc[i][j] += av[i] * bv[j];
        }
        __syncthreads();
    }
    int b = s0 >> 11, sr = (s0 & 2047) + tx * 4;
#pragma unroll
    for (int i = 0; i < 4; i++) {
        int c = c0 + ty * 4 + i;
        size_t elem = ((size_t)(b * Dd + c)) * Sq + sr;
        float h0 = __bfloat162float(__float2bfloat16(acc[i][0]));
        float h1 = __bfloat162float(__float2bfloat16(acc[i][1]));
        float h2 = __bfloat162float(__float2bfloat16(acc[i][2]));
        float h3 = __bfloat162float(__float2bfloat16(acc[i][3]));
        ((uint2*)g_eth)[elem >> 2] = make_uint2(pack_bf16(h0, h1), pack_bf16(h2, h3));
        ((uint2*)g_etl)[elem >> 2] = make_uint2(pack_bf16(acc[i][0] - h0, acc[i][1] - h1),
                                                pack_bf16(acc[i][2] - h2, acc[i][3] - h3));
    }
}

// ---------------- kernel 4: mma.sync attention ----------------
// smem byte offsets
#define SQH 0        // Q hi  [128][512B] xor-swizzled
#define SQL 65536
#define SKH 131072   // K hi  [32][512B] xor-swizzled
#define SKL 147456
#define SEH 163840   // E hi  [256 cols][80B] (64B data + 16 pad)
#define SEL 184320
#define SPH 204800   // P hi  [128][80B] (b32-packed pairs, 20 u32/row)
#define SPL 215040
#define SDN 225280   // 256 floats: [half][row]
#define SM_TOTAL 226304

__global__ __launch_bounds__(512, 1) void attn_mma_kernel(float* __restrict__ Out) {
    extern __shared__ char smem[];
    unsigned sb = smem_u32(smem);
    int tid = threadIdx.x, w = tid >> 5, lane = tid & 31;
    int g = lane >> 2, t = lane & 3;
    int wp = w >> 1;          // warp pair: q-rows wp*16..+15
    int nh = w & 1;           // key-half (MMA1) / col-half (MMA2)
    int bx = blockIdx.x;
    int m = 15 - (bx >> 3);
    int b = bx & 7;
    int q0 = m * 128;

    // ---- load Q (rows q0+1..q0+128), hi/lo, xor-swizzled, stride 512B
    {
        int r = tid >> 2;
        int cp = (tid & 3) * 8;
        const uint4* srcH = (const uint4*)g_ph + ((size_t)(b * (Sq + 1) + q0 + 1 + r)) * 32 + cp;
        const uint4* srcL = (const uint4*)g_pl + ((size_t)(b * (Sq + 1) + q0 + 1 + r)) * 32 + cp;
#pragma unroll
        for (int j = 0; j < 8; j++) {
            unsigned pc = (unsigned)((cp + j) ^ (r & 7));
            *(uint4*)(smem + SQH + r * 512 + pc * 16) = srcH[j];
            *(uint4*)(smem + SQL + r * 512 + pc * 16) = srcL[j];
        }
    }

    float acc[64];
#pragma unroll
    for (int i = 0; i < 64; i++) acc[i] = 0.f;
    float dsum0 = 0.f, dsum1 = 0.f;

    // precomputed ldmatrix bases
    int aRow = wp * 16 + (lane & 15);
    unsigned qbH = sb + SQH + aRow * 512;
    unsigned qbL = sb + SQL + aRow * 512;
    int krow = nh * 16 + ((lane >> 4) << 3) + (lane & 7);
    unsigned kbH = sb + SKH + krow * 512;
    unsigned kbL = sb + SKL + krow * 512;
    int l7 = lane & 7;
    int asel = lane >> 4;            // 0/1
    int bsel = (lane >> 3) & 1;      // 0/1
    int erow = nh * 128 + ((lane >> 4) << 3) + (lane & 7);
    unsigned ebH = sb + SEH + erow * 80 + bsel * 16;
    unsigned ebL = sb + SEL + erow * 80 + bsel * 16;
    unsigned* P32h = (unsigned*)(smem + SPH);
    unsigned* P32l = (unsigned*)(smem + SPL);
    int prow0 = (wp * 16 + g) * 20;
    int prow1 = prow0 + 160;

    int kend = q0 + 128;
    for (int kb = 0; kb < kend; kb += 32) {
        __syncthreads();
        // K tile: 32 rows x 512B hi/lo, swizzled
        {
            int r = tid >> 4;
            int c0 = (tid & 15) * 2;
            const uint4* sH = (const uint4*)g_ph + ((size_t)(b * (Sq + 1) + kb + r)) * 32 + c0;
            const uint4* sL = (const uint4*)g_pl + ((size_t)(b * (Sq + 1) + kb + r)) * 32 + c0;
            unsigned p0 = (unsigned)(c0 ^ (r & 7)), p1 = (unsigned)((c0 + 1) ^ (r & 7));
            *(uint4*)(smem + SKH + r * 512 + p0 * 16) = sH[0];
            *(uint4*)(smem + SKH + r * 512 + p1 * 16) = sH[1];
            *(uint4*)(smem + SKL + r * 512 + p0 * 16) = sL[0];
            *(uint4*)(smem + SKL + r * 512 + p1 * 16) = sL[1];
        }
        // E tile: 256 rows(c) x 64B keys, stride 80
        {
            int r = tid >> 1, hf = tid & 1;
            size_t gu = ((size_t)(b * Dd + r)) * 256 + (kb >> 3) + hf * 2;
            char* dh = smem + SEH + r * 80 + hf * 32;
            char* dl = smem + SEL + r * 80 + hf * 32;
            *(uint4*)dh        = ((const uint4*)g_eth)[gu];
            *(uint4*)(dh + 16) = ((const uint4*)g_eth)[gu + 1];
            *(uint4*)dl        = ((const uint4*)g_etl)[gu];
            *(uint4*)(dl + 16) = ((const uint4*)g_etl)[gu + 1];
        }
        __syncthreads();

        // ---- MMA1: S[16 x 16keys] for this warp (2 n-tiles)
        float S[8];
#pragma unroll
        for (int i = 0; i < 8; i++) S[i] = 0.f;
#pragma unroll
        for (int ks = 0; ks < 16; ks++) {
            unsigned ach = (unsigned)(((2 * ks + asel) ^ l7) << 4);
            unsigned bch = (unsigned)(((2 * ks + bsel) ^ l7) << 4);
            unsigned ah[4], al[4], bh[4], bl[4];
            ldsm4(ah, qbH + ach);
            ldsm4(bh, kbH + bch);
            ldsm4(al, qbL + ach);
            ldsm4(bl, kbL + bch);
            mma16816(S,     ah, bh[0], bh[1]);
            mma16816(S + 4, ah, bh[2], bh[3]);
            mma16816(S,     ah, bl[0], bl[1]);
            mma16816(S + 4, ah, bl[2], bl[3]);
            mma16816(S,     al, bh[0], bh[1]);
            mma16816(S + 4, al, bh[2], bh[3]);
        }
        // ---- exp epilogue -> P smem (hi/lo), denom accumulate
        int r0 = q0 + wp * 16 + g, r1 = r0 + 8;
#pragma unroll
        for (int j = 0; j < 2; j++) {
            int c0c = kb + nh * 16 + j * 8 + 2 * t;
            float v0 = fminf(fmaxf(S[j * 4 + 0] * 0.0625f, -10.f), 10.f);
            float v1 = fminf(fmaxf(S[j * 4 + 1] * 0.0625f, -10.f), 10.f);
            float v2 = fminf(fmaxf(S[j * 4 + 2] * 0.0625f, -10.f), 10.f);
            float v3 = fminf(fmaxf(S[j * 4 + 3] * 0.0625f, -10.f), 10.f);
            float p0 = (c0c     <= r0) ? __expf(v0) : 0.f;
            float p1 = (c0c + 1 <= r0) ? __expf(v1) : 0.f;
            float p2 = (c0c     <= r1) ? __expf(v2) : 0.f;
            float p3 = (c0c + 1 <= r1) ? __expf(v3) : 0.f;
            dsum0 += p0 + p1;
            dsum1 += p2 + p3;
            float h0 = __bfloat162float(__float2bfloat16(p0));
            float h1 = __bfloat162float(__float2bfloat16(p1));
            float h2 = __bfloat162float(__float2bfloat16(p2));
            float h3 = __bfloat162float(__float2bfloat16(p3));
            int c32 = nh * 8 + j * 4 + t;
            P32h[prow0 + c32] = pack_bf16(h0, h1);
            P32h[prow1 + c32] = pack_bf16(h2, h3);
            P32l[prow0 + c32] = pack_bf16(p0 - h0, p1 - h1);
            P32l[prow1 + c32] = pack_bf16(p2 - h2, p3 - h3);
        }
        __syncthreads();

        // ---- MMA2: acc[16 x 128cols] += P[16x32] . E2t
#pragma unroll
        for (int ks = 0; ks < 2; ks++) {
            unsigned ph[4], pl[4];
            ph[0] = P32h[prow0 + ks * 8 + t];
            ph[1] = P32h[prow1 + ks * 8 + t];
            ph[2] = P32h[prow0 + ks * 8 + 4 + t];
            ph[3] = P32h[prow1 + ks * 8 + 4 + t];
            pl[0] = P32l[prow0 + ks * 8 + t];
            pl[1] = P32l[prow1 + ks * 8 + t];
            pl[2] = P32l[prow0 + ks * 8 + 4 + t];
            pl[3] = P32l[prow1 + ks * 8 + 4 + t];
#pragma unroll
            for (int jp = 0; jp < 8; jp++) {
                unsigned eo = (unsigned)(jp * 1280 + ks * 32);
                unsigned eh[4], el[4];
                ldsm4(eh, ebH + eo);
                ldsm4(el, ebL + eo);
                mma16816(acc + jp * 8,     ph, eh[0], eh[1]);
                mma16816(acc + jp * 8 + 4, ph, eh[2], eh[3]);
                mma16816(acc + jp * 8,     pl, eh[0], eh[1]);
                mma16816(acc + jp * 8 + 4, pl, eh[2], eh[3]);
                mma16816(acc + jp * 8,     ph, el[0], el[1]);
                mma16816(acc + jp * 8 + 4, ph, el[2], el[3]);
            }
        }
    }

    // ---- denominators: quad reduce, write per-half slot
    dsum0 += __shfl_xor_sync(0xFFFFFFFF, dsum0, 1);
    dsum0 += __shfl_xor_sync(0xFFFFFFFF, dsum0, 2);
    dsum1 += __shfl_xor_sync(0xFFFFFFFF, dsum1, 1);
    dsum1 += __shfl_xor_sync(0xFFFFFFFF, dsum1, 2);
    float* Dn = (float*)(smem + SDN);
    if (t == 0) {
        Dn[nh * 128 + wp * 16 + g] = dsum0;
        Dn[nh * 128 + wp * 16 + g + 8] = dsum1;
    }
    __syncthreads();

    // ---- output
    {
        int lr0 = wp * 16 + g, lr1 = lr0 + 8;
        int r0 = q0 + lr0, r1 = q0 + lr1;
        float inv0 = 1.f / ((float)(r0 + 1) * (Dn[lr0] + Dn[128 + lr0]));
        float inv1 = 1.f / ((float)(r1 + 1) * (Dn[lr1] + Dn[128 + lr1]));
        float* o0 = Out + ((size_t)(b * Sq + r0)) * 256;
        float* o1 = Out + ((size_t)(b * Sq + r1)) * 256;
#pragma unroll
        for (int j = 0; j < 16; j++) {
            int col = nh * 128 + j * 8 + 2 * t;
            float2 v0 = make_float2(acc[j * 4 + 0] * inv0, acc[j * 4 + 1] * inv0);
            float2 v1 = make_float2(acc[j * 4 + 2] * inv1, acc[j * 4 + 3] * inv1);
            *(float2*)(o0 + col) = v0;
            *(float2*)(o1 + col) = v1;
        }
    }
}

// ---------------------------------------------------------------------------
extern "C" void kernel_launch(void* const* d_in, const int* in_sizes, int n_in,
                              void* d_out, int out_size) {
    const float* e  = (const float*)d_in[0];
    const float* p  = (const float*)d_in[1];
    const float* Wo = (const float*)d_in[2];
    float* out = (float*)d_out;

    cudaFuncSetAttribute(attn_mma_kernel, cudaFuncAttributeMaxDynamicSharedMemorySize, SM_TOTAL);

    weff_kernel<<<Dd, Dd>>>(Wo);
    pconv_kernel<<<(Bsz * (Sq + 1) * Dd) / 1024, 256>>>(p);
    e2t_gemm_kernel<<<dim3(Bsz * Sq / 64, Dd / 64), 256>>>(e);
    attn_mma_kernel<<<128, 512, SM_TOTAL>>>(out);
}

// round 5
// speedup vs baseline: 2.6362x; 1.3305x over previous
#include <cuda_runtime.h>
#include <cuda_bf16.h>

#define Bsz 8
#define Sq  2048
#define Dd  256

__device__ float g_weff[Dd * Dd];
__device__ unsigned short g_ph[(size_t)Bsz * (Sq + 1) * Dd];
__device__ unsigned short g_pl[(size_t)Bsz * (Sq + 1) * Dd];
__device__ unsigned short g_eth[(size_t)Bsz * Dd * Sq];
__device__ unsigned short g_etl[(size_t)Bsz * Dd * Sq];
// split-k partials: slot = ((b*24 + (m-8))*4 + s), each 64x256 acc + 64 dn
__device__ float g_pacc[768 * 64 * 256];
__device__ float g_pdn[768 * 64];

// unit tables: 80 units/batch sorted by size desc
__device__ const signed char U_M[80] = {
    31,31,31,31, 30,30,30, 29,29,29, 28,28,28, 27,27,27, 26,26,26, 25,25,25,
    24,24,24, 23,23,23, 22,22, 21,21, 20,20, 19,19, 18,18, 17,17, 16,16, 15,15,
    14,13,12,11,10,9,8,7,
    30,22,14,6, 29,21,13,5, 28,20,12,4, 27,19,11,3, 26,18,10,2, 25,17,9,1, 24,16,8,0};
__device__ const signed char U_S[80] = {
    0,1,2,3, 0,1,2, 0,1,2, 0,1,2, 0,1,2, 0,1,2, 0,1,2,
    0,1,2, 0,1,2, 0,1, 0,1, 0,1, 0,1, 0,1, 0,1, 0,1, 0,1,
    0,0,0,0,0,0,0,0,
    3,2,1,0, 3,2,1,0, 3,2,1,0, 3,2,1,0, 3,2,1,0, 3,2,1,0, 3,2,1,0};

__device__ __forceinline__ unsigned pack_bf16(float a, float b) {
    __nv_bfloat162 t = __floats2bfloat162_rn(a, b);
    return *(unsigned*)&t;
}
__device__ __forceinline__ void mma16816(float* d, const unsigned* a, unsigned b0, unsigned b1) {
    asm volatile("mma.sync.aligned.m16n8k16.row.col.f32.bf16.bf16.f32 "
        "{%0,%1,%2,%3}, {%4,%5,%6,%7}, {%8,%9}, {%0,%1,%2,%3};"
        : "+f"(d[0]), "+f"(d[1]), "+f"(d[2]), "+f"(d[3])
        : "r"(a[0]), "r"(a[1]), "r"(a[2]), "r"(a[3]), "r"(b0), "r"(b1));
}
__device__ __forceinline__ void ldsm4(unsigned* r, unsigned addr) {
    asm volatile("ldmatrix.sync.aligned.m8n8.x4.shared.b16 {%0,%1,%2,%3}, [%4];"
        : "=r"(r[0]), "=r"(r[1]), "=r"(r[2]), "=r"(r[3]) : "r"(addr));
}
__device__ __forceinline__ unsigned smem_u32(const void* p) {
    unsigned a;
    asm("{ .reg .u64 t; cvta.to.shared.u64 t, %1; cvt.u32.u64 %0, t; }" : "=r"(a) : "l"(p));
    return a;
}
__device__ __forceinline__ void cpasync16(unsigned dst, const void* src) {
    asm volatile("cp.async.cg.shared.global [%0], [%1], 16;" :: "r"(dst), "l"(src));
}
#define CP_COMMIT_WAIT() asm volatile("cp.async.commit_group;\ncp.async.wait_group 0;" ::: "memory")

// ---------------- kernel 1: W_eff fold ----------------
__global__ void weff_kernel(const float* __restrict__ Wo) {
    int d = blockIdx.x, dp = threadIdx.x;
    float s = 0.f;
#pragma unroll
    for (int h = 0; h < 8; h++) s += Wo[(size_t)d * (Dd * 8) + h * Dd + dp];
    g_weff[d * Dd + dp] = s;
}

// ---------------- kernel 2: p -> bf16 hi/lo ----------------
__global__ void pconv_kernel(const float* __restrict__ P) {
    size_t i = (size_t)blockIdx.x * 256 + threadIdx.x;
    float4 v = ((const float4*)P)[i];
    float hx = __bfloat162float(__float2bfloat16(v.x));
    float hy = __bfloat162float(__float2bfloat16(v.y));
    float hz = __bfloat162float(__float2bfloat16(v.z));
    float hw = __bfloat162float(__float2bfloat16(v.w));
    ((uint2*)g_ph)[i] = make_uint2(pack_bf16(hx, hy), pack_bf16(hz, hw));
    ((uint2*)g_pl)[i] = make_uint2(pack_bf16(v.x - hx, v.y - hy), pack_bf16(v.z - hz, v.w - hw));
}

// ---------------- kernel 3: e2t[b][c][s] ----------------
__global__ void e2t_gemm_kernel(const float* __restrict__ E) {
    __shared__ float As[32][68], Bs[32][68];
    int tid = threadIdx.x;
    int s0 = blockIdx.x * 64, c0 = blockIdx.y * 64;
    int ty = tid >> 4, tx = tid & 15, lr = tid >> 5, lc = tid & 31;
    float acc[4][4];
#pragma unroll
    for (int i = 0; i < 4; i++)
#pragma unroll
        for (int j = 0; j < 4; j++) acc[i][j] = 0.f;
    for (int k0 = 0; k0 < Dd; k0 += 32) {
#pragma unroll
        for (int i = 0; i < 8; i++) {
            int row = lr + i * 8;
            As[lc][row] = g_weff[(size_t)(c0 + row) * Dd + k0 + lc];
            Bs[lc][row] = E[(size_t)(s0 + row) * Dd + k0 + lc];
        }
        __syncthreads();
#pragma unroll
        for (int kk = 0; kk < 32; kk++) {
            float4 a = *(const float4*)&As[kk][ty * 4];
            float4 b = *(const float4*)&Bs[kk][tx * 4];
            float av[4] = {a.x, a.y, a.z, a.w}, bv[4] = {b.x, b.y, b.z, b.w};
#pragma unroll
            for (int i = 0; i < 4; i++)
#pragma unroll
                for (int j = 0; j < 4; j++) acc[i][j] += av[i] * bv[j];
        }
        __syncthreads();
    }
    int b = s0 >> 11, sr = (s0 & 2047) + tx * 4;
#pragma unroll
    for (int i = 0; i < 4; i++) {
        int c = c0 + ty * 4 + i;
        size_t elem = ((size_t)(b * Dd + c)) * Sq + sr;
        float h0 = __bfloat162float(__float2bfloat16(acc[i][0]));
        float h1 = __bfloat162float(__float2bfloat16(acc[i][1]));
        float h2 = __bfloat162float(__float2bfloat16(acc[i][2]));
        float h3 = __bfloat162float(__float2bfloat16(acc[i][3]));
        ((uint2*)g_eth)[elem >> 2] = make_uint2(pack_bf16(h0, h1), pack_bf16(h2, h3));
        ((uint2*)g_etl)[elem >> 2] = make_uint2(pack_bf16(acc[i][0] - h0, acc[i][1] - h1),
                                                pack_bf16(acc[i][2] - h2, acc[i][3] - h3));
    }
}

// ---------------- kernel 4: attention units ----------------
// smem: Q 64x512 hi/lo | K 64x512 hi/lo | E 256x144 hi/lo | P 64x37u32 hi/lo | Dn 256
#define SQH 0
#define SQL 32768
#define SKH 65536
#define SKL 98304
#define SEH 131072
#define SEL 167936
#define SPH 204800
#define SPL 214272
#define SDN 223744
#define SM_TOTAL 224768
#define PSTR 37

__global__ __launch_bounds__(512, 1) void attn_mma_kernel(float* __restrict__ Out) {
    extern __shared__ char smem[];
    unsigned sb = smem_u32(smem);
    int tid = threadIdx.x, w = tid >> 5, lane = tid & 31;
    int g = lane >> 2, t = lane & 3;
    int quad = w >> 2;          // q-rows quad*16..+15
    int role = w & 3;           // key-quarter (MMA1) / col-quarter (MMA2)

    int u = blockIdx.x;
    int b = u & 7, idx = u >> 3;
    int m = U_M[idx], s = U_S[idx];
    int q0 = m * 64;
    int k0 = s * 512;
    int kendU = (m + 1) * 64;
    if (kendU > k0 + 512) kendU = k0 + 512;
    bool finalTile = (m <= 7);

    // ---- load Q (rows q0+1..q0+64), hi/lo, swizzled, stride 512B
    {
        int r = tid >> 3;
        int cp = (tid & 7) * 4;
        const uint4* srcH = (const uint4*)g_ph + ((size_t)(b * (Sq + 1) + q0 + 1 + r)) * 32 + cp;
        const uint4* srcL = (const uint4*)g_pl + ((size_t)(b * (Sq + 1) + q0 + 1 + r)) * 32 + cp;
#pragma unroll
        for (int j = 0; j < 4; j++) {
            unsigned pc = (unsigned)((cp + j) ^ (r & 7));
            *(uint4*)(smem + SQH + r * 512 + pc * 16) = srcH[j];
            *(uint4*)(smem + SQL + r * 512 + pc * 16) = srcL[j];
        }
    }

    float acc[32];
#pragma unroll
    for (int i = 0; i < 32; i++) acc[i] = 0.f;
    float dsum0 = 0.f, dsum1 = 0.f;

    int aRow = quad * 16 + (lane & 15);
    unsigned qbH = sb + SQH + aRow * 512;
    unsigned qbL = sb + SQL + aRow * 512;
    int krow = role * 16 + ((lane >> 4) << 3) + (lane & 7);
    unsigned kbH = sb + SKH + krow * 512;
    unsigned kbL = sb + SKL + krow * 512;
    int l7 = lane & 7;
    int asel = lane >> 4;
    int bsel = (lane >> 3) & 1;
    int erow = role * 64 + ((lane >> 4) << 3) + (lane & 7);
    unsigned ebH = sb + SEH + erow * 144 + bsel * 16;
    unsigned ebL = sb + SEL + erow * 144 + bsel * 16;
    unsigned* P32h = (unsigned*)(smem + SPH);
    unsigned* P32l = (unsigned*)(smem + SPL);
    int prow0 = (quad * 16 + g) * PSTR;
    int prow1 = prow0 + 8 * PSTR;

    // cp.async index precompute
    int krr = tid >> 3, kcp = (tid & 7) * 4;
    size_t kgu_base = ((size_t)(b * (Sq + 1) + krr)) * 32;
    int err_ = tid >> 1, ehf = tid & 1;
    size_t egu_base = (size_t)(b * 256 + err_) * 256;
    unsigned edst = sb + (ehf ? SEL : SEH) + err_ * 144;

    for (int kb = k0; kb < kendU; kb += 64) {
        __syncthreads();
        // K tile via cp.async (hi+lo), swizzled
        {
            size_t gu = kgu_base + (size_t)kb * 32;
#pragma unroll
            for (int j = 0; j < 4; j++) {
                int c4 = kcp + j;
                unsigned pc = (unsigned)(c4 ^ (krr & 7));
                cpasync16(sb + SKH + krr * 512 + pc * 16, (const uint4*)g_ph + gu + c4);
                cpasync16(sb + SKL + krr * 512 + pc * 16, (const uint4*)g_pl + gu + c4);
            }
        }
        // E tile via cp.async: row=col c, 64 keys (128B), hi or lo per thread
        {
            const unsigned short* gsrc = ehf ? g_etl : g_eth;
            size_t gu = egu_base + (kb >> 3);
#pragma unroll
            for (int j = 0; j < 8; j++)
                cpasync16(edst + j * 16, (const uint4*)gsrc + gu + j);
        }
        CP_COMMIT_WAIT();
        __syncthreads();

        // ---- MMA1: S[16 x 16keys] (role's key window)
        float S[8];
#pragma unroll
        for (int i = 0; i < 8; i++) S[i] = 0.f;
#pragma unroll
        for (int ks = 0; ks < 16; ks++) {
            unsigned ach = (unsigned)(((2 * ks + asel) ^ l7) << 4);
            unsigned bch = (unsigned)(((2 * ks + bsel) ^ l7) << 4);
            unsigned ah[4], al[4], bh[4], bl[4];
            ldsm4(ah, qbH + ach);
            ldsm4(bh, kbH + bch);
            ldsm4(al, qbL + ach);
            ldsm4(bl, kbL + bch);
            mma16816(S,     ah, bh[0], bh[1]);
            mma16816(S + 4, ah, bh[2], bh[3]);
            mma16816(S,     ah, bl[0], bl[1]);
            mma16816(S + 4, ah, bl[2], bl[3]);
            mma16816(S,     al, bh[0], bh[1]);
            mma16816(S + 4, al, bh[2], bh[3]);
        }
        // ---- exp epilogue -> P smem
        int r0 = q0 + quad * 16 + g, r1 = r0 + 8;
#pragma unroll
        for (int j = 0; j < 2; j++) {
            int c0c = kb + role * 16 + j * 8 + 2 * t;
            float v0 = fminf(fmaxf(S[j * 4 + 0] * 0.0625f, -10.f), 10.f);
            float v1 = fminf(fmaxf(S[j * 4 + 1] * 0.0625f, -10.f), 10.f);
            float v2 = fminf(fmaxf(S[j * 4 + 2] * 0.0625f, -10.f), 10.f);
            float v3 = fminf(fmaxf(S[j * 4 + 3] * 0.0625f, -10.f), 10.f);
            float p0 = (c0c     <= r0) ? __expf(v0) : 0.f;
            float p1 = (c0c + 1 <= r0) ? __expf(v1) : 0.f;
            float p2 = (c0c     <= r1) ? __expf(v2) : 0.f;
            float p3 = (c0c + 1 <= r1) ? __expf(v3) : 0.f;
            dsum0 += p0 + p1;
            dsum1 += p2 + p3;
            float h0 = __bfloat162float(__float2bfloat16(p0));
            float h1 = __bfloat162float(__float2bfloat16(p1));
            float h2 = __bfloat162float(__float2bfloat16(p2));
            float h3 = __bfloat162float(__float2bfloat16(p3));
            int c32 = role * 8 + j * 4 + t;
            P32h[prow0 + c32] = pack_bf16(h0, h1);
            P32h[prow1 + c32] = pack_bf16(h2, h3);
            P32l[prow0 + c32] = pack_bf16(p0 - h0, p1 - h1);
            P32l[prow1 + c32] = pack_bf16(p2 - h2, p3 - h3);
        }
        // quad-scope barrier: P ready
        asm volatile("bar.sync %0, 128;" :: "r"(quad + 1) : "memory");

        // ---- MMA2: acc[16 x 64cols] += P[16x64] . E2t (role's col window)
#pragma unroll
        for (int ks = 0; ks < 4; ks++) {
            unsigned ph[4], pl[4];
            ph[0] = P32h[prow0 + ks * 8 + t];
            ph[1] = P32h[prow1 + ks * 8 + t];
            ph[2] = P32h[prow0 + ks * 8 + 4 + t];
            ph[3] = P32h[prow1 + ks * 8 + 4 + t];
            pl[0] = P32l[prow0 + ks * 8 + t];
            pl[1] = P32l[prow1 + ks * 8 + t];
            pl[2] = P32l[prow0 + ks * 8 + 4 + t];
            pl[3] = P32l[prow1 + ks * 8 + 4 + t];
#pragma unroll
            for (int jp = 0; jp < 4; jp++) {
                unsigned eo = (unsigned)(jp * 2304 + ks * 32);
                unsigned eh[4], el[4];
                ldsm4(eh, ebH + eo);
                ldsm4(el, ebL + eo);
                mma16816(acc + jp * 8,     ph, eh[0], eh[1]);
                mma16816(acc + jp * 8 + 4, ph, eh[2], eh[3]);
                mma16816(acc + jp * 8,     pl, eh[0], eh[1]);
                mma16816(acc + jp * 8 + 4, pl, eh[2], eh[3]);
                mma16816(acc + jp * 8,     ph, el[0], el[1]);
                mma16816(acc + jp * 8 + 4, ph, el[2], el[3]);
            }
        }
    }

    // ---- denominators
    dsum0 += __shfl_xor_sync(0xFFFFFFFF, dsum0, 1);
    dsum0 += __shfl_xor_sync(0xFFFFFFFF, dsum0, 2);
    dsum1 += __shfl_xor_sync(0xFFFFFFFF, dsum1, 1);
    dsum1 += __shfl_xor_sync(0xFFFFFFFF, dsum1, 2);
    float* Dn = (float*)(smem + SDN);
    if (t == 0) {
        Dn[role * 64 + quad * 16 + g] = dsum0;
        Dn[role * 64 + quad * 16 + g + 8] = dsum1;
    }
    __syncthreads();

    int lr0 = quad * 16 + g, lr1 = lr0 + 8;
    float d0 = Dn[lr0] + Dn[64 + lr0] + Dn[128 + lr0] + Dn[192 + lr0];
    float d1 = Dn[lr1] + Dn[64 + lr1] + Dn[128 + lr1] + Dn[192 + lr1];

    if (finalTile) {
        int r0 = q0 + lr0, r1 = q0 + lr1;
        float inv0 = 1.f / ((float)(r0 + 1) * d0);
        float inv1 = 1.f / ((float)(r1 + 1) * d1);
        float* o0 = Out + ((size_t)(b * Sq + r0)) * 256;
        float* o1 = Out + ((size_t)(b * Sq + r1)) * 256;
#pragma unroll
        for (int j = 0; j < 8; j++) {
            int col = role * 64 + j * 8 + 2 * t;
            *(float2*)(o0 + col) = make_float2(acc[j * 4 + 0] * inv0, acc[j * 4 + 1] * inv0);
            *(float2*)(o1 + col) = make_float2(acc[j * 4 + 2] * inv1, acc[j * 4 + 3] * inv1);
        }
    } else {
        int slot = (b * 24 + (m - 8)) * 4 + s;
        float* pa = g_pacc + (size_t)slot * 16384;
        if (t == 0) {
            if (role == 0) {
                g_pdn[slot * 64 + lr0] = d0;
                g_pdn[slot * 64 + lr1] = d1;
            }
        }
#pragma unroll
        for (int j = 0; j < 8; j++) {
            int col = role * 64 + j * 8 + 2 * t;
            *(float2*)(pa + lr0 * 256 + col) = make_float2(acc[j * 4 + 0], acc[j * 4 + 1]);
            *(float2*)(pa + lr1 * 256 + col) = make_float2(acc[j * 4 + 2], acc[j * 4 + 3]);
        }
    }
}

// ---------------- kernel 5: reduce split-k partials (m >= 8) ----------------
__global__ void reduce_kernel(float* __restrict__ Out) {
    __shared__ float dns[64];
    int tile = blockIdx.x;           // 0..191
    int b = tile / 24, m = (tile % 24) + 8;
    int cnt = (m + 8) >> 3;
    int slot0 = (b * 24 + (m - 8)) * 4;
    int tid = threadIdx.x;
    if (tid < 64) {
        float d = 0.f;
        for (int s = 0; s < cnt; s++) d += g_pdn[(slot0 + s) * 64 + tid];
        dns[tid] = d;
    }
    __syncthreads();
    int q0 = m * 64;
    for (int i = tid; i < 16384; i += 256) {
        int r = i >> 8, c = i & 255;
        float a = 0.f;
        for (int s = 0; s < cnt; s++) a += g_pacc[(size_t)(slot0 + s) * 16384 + i];
        int q = q0 + r;
        Out[((size_t)(b * Sq + q)) * 256 + c] = a / ((float)(q + 1) * dns[r]);
    }
}

// ---------------------------------------------------------------------------
extern "C" void kernel_launch(void* const* d_in, const int* in_sizes, int n_in,
                              void* d_out, int out_size) {
    const float* e  = (const float*)d_in[0];
    const float* p  = (const float*)d_in[1];
    const float* Wo = (const float*)d_in[2];
    float* out = (float*)d_out;

    cudaFuncSetAttribute(attn_mma_kernel, cudaFuncAttributeMaxDynamicSharedMemorySize, SM_TOTAL);

    weff_kernel<<<Dd, Dd>>>(Wo);
    pconv_kernel<<<(Bsz * (Sq + 1) * Dd) / 1024, 256>>>(p);
    e2t_gemm_kernel<<<dim3(Bsz * Sq / 64, Dd / 64), 256>>>(e);
    attn_mma_kernel<<<640, 512, SM_TOTAL>>>(out);
    reduce_kernel<<<192, 256>>>(out);
}

// round 9
// speedup vs baseline: 2.8338x; 1.0749x over previous
#include <cuda_runtime.h>
#include <cuda_bf16.h>

#define Bsz 8
#define Sq  2048
#define Dd  256

__device__ unsigned short g_wh[Dd * Dd];
__device__ unsigned short g_wl[Dd * Dd];
__device__ unsigned short g_ph[(size_t)Bsz * (Sq + 1) * Dd];
__device__ unsigned short g_pl[(size_t)Bsz * (Sq + 1) * Dd];
__device__ unsigned short g_eh[(size_t)Bsz * Sq * Dd];
__device__ unsigned short g_el[(size_t)Bsz * Sq * Dd];
__device__ unsigned short g_eth[(size_t)Bsz * Dd * Sq];
__device__ unsigned short g_etl[(size_t)Bsz * Dd * Sq];
__device__ float g_pacc[768 * 64 * 256];
__device__ float g_pdn[768 * 64];

__device__ const signed char U_M[80] = {
    31,31,31,31, 30,30,30, 29,29,29, 28,28,28, 27,27,27, 26,26,26, 25,25,25,
    24,24,24, 23,23,23, 22,22, 21,21, 20,20, 19,19, 18,18, 17,17, 16,16, 15,15,
    14,13,12,11,10,9,8,7,
    30,22,14,6, 29,21,13,5, 28,20,12,4, 27,19,11,3, 26,18,10,2, 25,17,9,1, 24,16,8,0};
__device__ const signed char U_S[80] = {
    0,1,2,3, 0,1,2, 0,1,2, 0,1,2, 0,1,2, 0,1,2, 0,1,2,
    0,1,2, 0,1,2, 0,1, 0,1, 0,1, 0,1, 0,1, 0,1, 0,1, 0,1,
    0,0,0,0,0,0,0,0,
    3,2,1,0, 3,2,1,0, 3,2,1,0, 3,2,1,0, 3,2,1,0, 3,2,1,0, 3,2,1,0};

__device__ __forceinline__ unsigned pack_bf16(float a, float b) {
    __nv_bfloat162 t = __floats2bfloat162_rn(a, b);
    return *(unsigned*)&t;
}
__device__ __forceinline__ void mma16816(float* d, const unsigned* a, unsigned b0, unsigned b1) {
    asm volatile("mma.sync.aligned.m16n8k16.row.col.f32.bf16.bf16.f32 "
        "{%0,%1,%2,%3}, {%4,%5,%6,%7}, {%8,%9}, {%0,%1,%2,%3};"
        : "+f"(d[0]), "+f"(d[1]), "+f"(d[2]), "+f"(d[3])
        : "r"(a[0]), "r"(a[1]), "r"(a[2]), "r"(a[3]), "r"(b0), "r"(b1));
}
__device__ __forceinline__ void ldsm4(unsigned* r, unsigned addr) {
    asm volatile("ldmatrix.sync.aligned.m8n8.x4.shared.b16 {%0,%1,%2,%3}, [%4];"
        : "=r"(r[0]), "=r"(r[1]), "=r"(r[2]), "=r"(r[3]) : "r"(addr));
}
__device__ __forceinline__ unsigned smem_u32(const void* p) {
    unsigned a;
    asm("{ .reg .u64 t; cvta.to.shared.u64 t, %1; cvt.u32.u64 %0, t; }" : "=r"(a) : "l"(p));
    return a;
}
__device__ __forceinline__ void cpasync16(unsigned dst, const void* src) {
    asm volatile("cp.async.cg.shared.global [%0], [%1], 16;" :: "r"(dst), "l"(src));
}
#define CP_COMMIT() asm volatile("cp.async.commit_group;" ::: "memory")
#define CP_WAIT1()  asm volatile("cp.async.wait_group 1;" ::: "memory")
#define CP_WAIT0()  asm volatile("cp.async.wait_group 0;" ::: "memory")

// ---------------- kernel 1: W_eff fold -> bf16 hi/lo ----------------
__global__ void weff_kernel(const float* __restrict__ Wo) {
    int d = blockIdx.x, dp = threadIdx.x;
    float s = 0.f;
#pragma unroll
    for (int h = 0; h < 8; h++) s += Wo[(size_t)d * (Dd * 8) + h * Dd + dp];
    __nv_bfloat16 hb = __float2bfloat16(s);
    float hf = __bfloat162float(hb);
    __nv_bfloat16 lb = __float2bfloat16(s - hf);
    g_wh[d * Dd + dp] = *(unsigned short*)&hb;
    g_wl[d * Dd + dp] = *(unsigned short*)&lb;
}

// ---------------- kernel 2: fp32 -> bf16 hi/lo (sel=0: p->g_ph/g_pl, sel=1: e->g_eh/g_el) ----
__global__ void conv_kernel(const float* __restrict__ X, int sel) {
    unsigned short* Hi = sel ? g_eh : g_ph;
    unsigned short* Lo = sel ? g_el : g_pl;
    size_t i = (size_t)blockIdx.x * 256 + threadIdx.x;
    float4 v = ((const float4*)X)[i];
    float hx = __bfloat162float(__float2bfloat16(v.x));
    float hy = __bfloat162float(__float2bfloat16(v.y));
    float hz = __bfloat162float(__float2bfloat16(v.z));
    float hw = __bfloat162float(__float2bfloat16(v.w));
    ((uint2*)Hi)[i] = make_uint2(pack_bf16(hx, hy), pack_bf16(hz, hw));
    ((uint2*)Lo)[i] = make_uint2(pack_bf16(v.x - hx, v.y - hy), pack_bf16(v.z - hz, v.w - hw));
}

// ---------------- kernel 3: e2t[b][c][s] via mma (3-pass bf16) ----------------
#define EWH 0
#define EWL 8192
#define EEH 16384
#define EEL 49152
#define EW_TOTAL 81920

__global__ __launch_bounds__(512, 1) void e2t_mma_kernel() {
    extern __shared__ char smem[];
    unsigned sb = smem_u32(smem);
    int tid = threadIdx.x, w = tid >> 5, lane = tid & 31;
    int g = lane >> 2, t = lane & 3;
    int cq = w >> 2, sr = w & 3;
    int bx = blockIdx.x;
    int b = bx >> 3, s_in = (bx & 7) * 256;
    int c0 = blockIdx.y * 64;

    int l7 = lane & 7;
    int asel = lane >> 4, bsel = (lane >> 3) & 1;
    int aRow = cq * 16 + (lane & 15);

    float acc[32];
#pragma unroll
    for (int i = 0; i < 32; i++) acc[i] = 0.f;

    int wr = tid >> 3, wcp = tid & 7;
    int er = tid >> 1, ehf = tid & 1;
    const unsigned short* egsrc = ehf ? g_el : g_eh;
    unsigned edst = sb + (ehf ? EEL : EEH) + er * 128;

    for (int kit = 0; kit < 4; kit++) {
        int k0 = kit * 64;
        __syncthreads();
        {   // W tile
            size_t gu = ((size_t)(c0 + wr) << 5) + (k0 >> 3) + wcp;
            unsigned pc = (unsigned)(wcp ^ (wr & 7));
            cpasync16(sb + EWH + wr * 128 + pc * 16, (const uint4*)g_wh + gu);
            cpasync16(sb + EWL + wr * 128 + pc * 16, (const uint4*)g_wl + gu);
        }
        {   // e tile
            size_t gu = ((size_t)(b * Sq + s_in + er) << 5) + (k0 >> 3);
#pragma unroll
            for (int j = 0; j < 8; j++) {
                unsigned pc = (unsigned)(j ^ (er & 7));
                cpasync16(edst + pc * 16, (const uint4*)egsrc + gu + j);
            }
        }
        CP_COMMIT();
        CP_WAIT0();
        __syncthreads();

#pragma unroll
        for (int ks = 0; ks < 4; ks++) {
            unsigned pca = (unsigned)((2 * ks + asel) ^ l7);
            unsigned ah[4], al[4];
            ldsm4(ah, sb + EWH + aRow * 128 + pca * 16);
            ldsm4(al, sb + EWL + aRow * 128 + pca * 16);
#pragma unroll
            for (int jn = 0; jn < 4; jn++) {
                int brow = sr * 64 + jn * 16 + ((lane >> 4) << 3) + (lane & 7);
                unsigned pcb = (unsigned)((2 * ks + bsel) ^ l7);
                unsigned bh[4], bl[4];
                ldsm4(bh, sb + EEH + brow * 128 + pcb * 16);
                ldsm4(bl, sb + EEL + brow * 128 + pcb * 16);
                mma16816(acc + jn * 8,     ah, bh[0], bh[1]);
                mma16816(acc + jn * 8 + 4, ah, bh[2], bh[3]);
                mma16816(acc + jn * 8,     ah, bl[0], bl[1]);
                mma16816(acc + jn * 8 + 4, ah, bl[2], bl[3]);
                mma16816(acc + jn * 8,     al, bh[0], bh[1]);
                mma16816(acc + jn * 8 + 4, al, bh[2], bh[3]);
            }
        }
    }

    int lr0 = cq * 16 + g, lr1 = lr0 + 8;
#pragma unroll
    for (int jn = 0; jn < 4; jn++)
#pragma unroll
        for (int h = 0; h < 2; h++) {
            int col = sr * 64 + jn * 16 + h * 8 + 2 * t;
            int s = s_in + col;
            float a0 = acc[jn * 8 + h * 4 + 0], a1 = acc[jn * 8 + h * 4 + 1];
            float a2 = acc[jn * 8 + h * 4 + 2], a3 = acc[jn * 8 + h * 4 + 3];
            float h0 = __bfloat162float(__float2bfloat16(a0));
            float h1 = __bfloat162float(__float2bfloat16(a1));
            float h2 = __bfloat162float(__float2bfloat16(a2));
            float h3 = __bfloat162float(__float2bfloat16(a3));
            size_t i0 = (((size_t)(b * Dd + c0 + lr0)) * Sq + s) >> 1;
            size_t i1 = (((size_t)(b * Dd + c0 + lr1)) * Sq + s) >> 1;
            ((unsigned*)g_eth)[i0] = pack_bf16(h0, h1);
            ((unsigned*)g_etl)[i0] = pack_bf16(a0 - h0, a1 - h1);
            ((unsigned*)g_eth)[i1] = pack_bf16(h2, h3);
            ((unsigned*)g_etl)[i1] = pack_bf16(a2 - h2, a3 - h3);
        }
}

// ---------------- kernel 4: attention units (pipelined) ----------------
#define SQH 0
#define SQL 32768
#define SKH 65536
#define SKL 98304
#define SEH 131072
#define SEL 167936
#define SPH 204800
#define SPL 214272
#define SDN 223744
#define SM_TOTAL 224768
#define PSTR 37

__global__ __launch_bounds__(512, 1) void attn_mma_kernel(float* __restrict__ Out) {
    extern __shared__ char smem[];
    unsigned sb = smem_u32(smem);
    int tid = threadIdx.x, w = tid >> 5, lane = tid & 31;
    int g = lane >> 2, t = lane & 3;
    int quad = w >> 2;
    int role = w & 3;

    int u = blockIdx.x;
    int b = u & 7, idx = u >> 3;
    int m = U_M[idx], s = U_S[idx];
    int q0 = m * 64;
    int k0 = s * 512;
    int kendU = (m + 1) * 64;
    if (kendU > k0 + 512) kendU = k0 + 512;
    bool finalTile = (m <= 7);

    // Q load
    {
        int r = tid >> 3;
        int cp = (tid & 7) * 4;
        const uint4* srcH = (const uint4*)g_ph + ((size_t)(b * (Sq + 1) + q0 + 1 + r)) * 32 + cp;
        const uint4* srcL = (const uint4*)g_pl + ((size_t)(b * (Sq + 1) + q0 + 1 + r)) * 32 + cp;
#pragma unroll
        for (int j = 0; j < 4; j++) {
            unsigned pc = (unsigned)((cp + j) ^ (r & 7));
            *(uint4*)(smem + SQH + r * 512 + pc * 16) = srcH[j];
            *(uint4*)(smem + SQL + r * 512 + pc * 16) = srcL[j];
        }
    }

    float acc[32];
#pragma unroll
    for (int i = 0; i < 32; i++) acc[i] = 0.f;
    float dsum0 = 0.f, dsum1 = 0.f;

    int aRow = quad * 16 + (lane & 15);
    unsigned qbH = sb + SQH + aRow * 512;
    unsigned qbL = sb + SQL + aRow * 512;
    int krow = role * 16 + ((lane >> 4) << 3) + (lane & 7);
    unsigned kbH = sb + SKH + krow * 512;
    unsigned kbL = sb + SKL + krow * 512;
    int l7 = lane & 7;
    int asel = lane >> 4;
    int bsel = (lane >> 3) & 1;
    int erow = role * 64 + ((lane >> 4) << 3) + (lane & 7);
    unsigned ebH = sb + SEH + erow * 144 + bsel * 16;
    unsigned ebL = sb + SEL + erow * 144 + bsel * 16;
    unsigned* P32h = (unsigned*)(smem + SPH);
    unsigned* P32l = (unsigned*)(smem + SPL);
    int prow0 = (quad * 16 + g) * PSTR;
    int prow1 = prow0 + 8 * PSTR;

    int krr = tid >> 3, kcp = (tid & 7) * 4;
    size_t kgu_base = ((size_t)(b * (Sq + 1) + krr)) * 32;
    int err_ = tid >> 1, ehf = tid & 1;
    size_t egu_base = (size_t)(b * 256 + err_) * 256;
    const unsigned short* egsrc = ehf ? g_etl : g_eth;
    unsigned edst = sb + (ehf ? SEL : SEH) + err_ * 144;

    auto issueK = [&](int kb) {
        size_t gu = kgu_base + (size_t)kb * 32;
#pragma unroll
        for (int j = 0; j < 4; j++) {
            int c4 = kcp + j;
            unsigned pc = (unsigned)(c4 ^ (krr & 7));
            cpasync16(sb + SKH + krr * 512 + pc * 16, (const uint4*)g_ph + gu + c4);
            cpasync16(sb + SKL + krr * 512 + pc * 16, (const uint4*)g_pl + gu + c4);
        }
        CP_COMMIT();
    };
    auto issueE = [&](int kb) {
        size_t gu = egu_base + (kb >> 3);
#pragma unroll
        for (int j = 0; j < 8; j++)
            cpasync16(edst + j * 16, (const uint4*)egsrc + gu + j);
        CP_COMMIT();
    };

    issueK(k0);
    issueE(k0);

    for (int kb = k0; kb < kendU; kb += 64) {
        bool more = (kb + 64 < kendU);
        CP_WAIT1();                 // K(kb) arrived
        __syncthreads();

        // ---- MMA1
        float S[8];
#pragma unroll
        for (int i = 0; i < 8; i++) S[i] = 0.f;
#pragma unroll
        for (int ks = 0; ks < 16; ks++) {
            unsigned ach = (unsigned)(((2 * ks + asel) ^ l7) << 4);
            unsigned bch = (unsigned)(((2 * ks + bsel) ^ l7) << 4);
            unsigned ah[4], al[4], bh[4], bl[4];
            ldsm4(ah, qbH + ach);
            ldsm4(bh, kbH + bch);
            ldsm4(al, qbL + ach);
            ldsm4(bl, kbL + bch);
            mma16816(S,     ah, bh[0], bh[1]);
            mma16816(S + 4, ah, bh[2], bh[3]);
            mma16816(S,     ah, bl[0], bl[1]);
            mma16816(S + 4, ah, bl[2], bl[3]);
            mma16816(S,     al, bh[0], bh[1]);
            mma16816(S + 4, al, bh[2], bh[3]);
        }
        __syncthreads();            // all warps done reading K
        if (more) issueK(kb + 64);  // K prefetch hides behind epilogue + MMA2

        // ---- exp epilogue
        int r0 = q0 + quad * 16 + g, r1 = r0 + 8;
#pragma unroll
        for (int j = 0; j < 2; j++) {
            int c0c = kb + role * 16 + j * 8 + 2 * t;
            float v0 = fminf(fmaxf(S[j * 4 + 0] * 0.0625f, -10.f), 10.f);
            float v1 = fminf(fmaxf(S[j * 4 + 1] * 0.0625f, -10.f), 10.f);
            float v2 = fminf(fmaxf(S[j * 4 + 2] * 0.0625f, -10.f), 10.f);
            float v3 = fminf(fmaxf(S[j * 4 + 3] * 0.0625f, -10.f), 10.f);
            float p0 = (c0c     <= r0) ? __expf(v0) : 0.f;
            float p1 = (c0c + 1 <= r0) ? __expf(v1) : 0.f;
            float p2 = (c0c     <= r1) ? __expf(v2) : 0.f;
            float p3 = (c0c + 1 <= r1) ? __expf(v3) : 0.f;
            dsum0 += p0 + p1;
            dsum1 += p2 + p3;
            float h0 = __bfloat162float(__float2bfloat16(p0));
            float h1 = __bfloat162float(__float2bfloat16(p1));
            float h2 = __bfloat162float(__float2bfloat16(p2));
            float h3 = __bfloat162float(__float2bfloat16(p3));
            int c32 = role * 8 + j * 4 + t;
            P32h[prow0 + c32] = pack_bf16(h0, h1);
            P32h[prow1 + c32] = pack_bf16(h2, h3);
            P32l[prow0 + c32] = pack_bf16(p0 - h0, p1 - h1);
            P32l[prow1 + c32] = pack_bf16(p2 - h2, p3 - h3);
        }
        if (more) CP_WAIT1(); else CP_WAIT0();   // E(kb) arrived
        __syncthreads();            // E + P visible CTA-wide

        // ---- MMA2
#pragma unroll
        for (int ks = 0; ks < 4; ks++) {
            unsigned ph[4], pl[4];
            ph[0] = P32h[prow0 + ks * 8 + t];
            ph[1] = P32h[prow1 + ks * 8 + t];
            ph[2] = P32h[prow0 + ks * 8 + 4 + t];
            ph[3] = P32h[prow1 + ks * 8 + 4 + t];
            pl[0] = P32l[prow0 + ks * 8 + t];
            pl[1] = P32l[prow1 + ks * 8 + t];
            pl[2] = P32l[prow0 + ks * 8 + 4 + t];
            pl[3] = P32l[prow1 + ks * 8 + 4 + t];
#pragma unroll
            for (int jp = 0; jp < 4; jp++) {
                unsigned eo = (unsigned)(jp * 2304 + ks * 32);
                unsigned eh[4], el[4];
                ldsm4(eh, ebH + eo);
                ldsm4(el, ebL + eo);
                mma16816(acc + jp * 8,     ph, eh[0], eh[1]);
                mma16816(acc + jp * 8 + 4, ph, eh[2], eh[3]);
                mma16816(acc + jp * 8,     pl, eh[0], eh[1]);
                mma16816(acc + jp * 8 + 4, pl, eh[2], eh[3]);
                mma16816(acc + jp * 8,     ph, el[0], el[1]);
                mma16816(acc + jp * 8 + 4, ph, el[2], el[3]);
            }
        }
        __syncthreads();            // all warps done reading E
        if (more) issueE(kb + 64);  // E prefetch hides behind next MMA1
    }

    // denominators
    dsum0 += __shfl_xor_sync(0xFFFFFFFF, dsum0, 1);
    dsum0 += __shfl_xor_sync(0xFFFFFFFF, dsum0, 2);
    dsum1 += __shfl_xor_sync(0xFFFFFFFF, dsum1, 1);
    dsum1 += __shfl_xor_sync(0xFFFFFFFF, dsum1, 2);
    float* Dn = (float*)(smem + SDN);
    if (t == 0) {
        Dn[role * 64 + quad * 16 + g] = dsum0;
        Dn[role * 64 + quad * 16 + g + 8] = dsum1;
    }
    __syncthreads();

    int lr0 = quad * 16 + g, lr1 = lr0 + 8;
    float d0 = Dn[lr0] + Dn[64 + lr0] + Dn[128 + lr0] + Dn[192 + lr0];
    float d1 = Dn[lr1] + Dn[64 + lr1] + Dn[128 + lr1] + Dn[192 + lr1];

    if (finalTile) {
        int r0 = q0 + lr0, r1 = q0 + lr1;
        float inv0 = 1.f / ((float)(r0 + 1) * d0);
        float inv1 = 1.f / ((float)(r1 + 1) * d1);
        float* o0 = Out + ((size_t)(b * Sq + r0)) * 256;
        float* o1 = Out + ((size_t)(b * Sq + r1)) * 256;
#pragma unroll
        for (int j = 0; j < 8; j++) {
            int col = role * 64 + j * 8 + 2 * t;
            *(float2*)(o0 + col) = make_float2(acc[j * 4 + 0] * inv0, acc[j * 4 + 1] * inv0);
            *(float2*)(o1 + col) = make_float2(acc[j * 4 + 2] * inv1, acc[j * 4 + 3] * inv1);
        }
    } else {
        int slot = (b * 24 + (m - 8)) * 4 + s;
        float* pa = g_pacc + (size_t)slot * 16384;
        if (t == 0 && role == 0) {
            g_pdn[slot * 64 + lr0] = d0;
            g_pdn[slot * 64 + lr1] = d1;
        }
#pragma unroll
        for (int j = 0; j < 8; j++) {
            int col = role * 64 + j * 8 + 2 * t;
            *(float2*)(pa + lr0 * 256 + col) = make_float2(acc[j * 4 + 0], acc[j * 4 + 1]);
            *(float2*)(pa + lr1 * 256 + col) = make_float2(acc[j * 4 + 2], acc[j * 4 + 3]);
        }
    }
}

// ---------------- kernel 5: reduce split-k partials ----------------
__global__ void reduce_kernel(float* __restrict__ Out) {
    __shared__ float dns[64];
    int tile = blockIdx.x;
    int b = tile / 24, m = (tile % 24) + 8;
    int cnt = (m + 8) >> 3;
    int slot0 = (b * 24 + (m - 8)) * 4;
    int tid = threadIdx.x;
    if (tid < 64) {
        float d = 0.f;
        for (int s = 0; s < cnt; s++) d += g_pdn[(slot0 + s) * 64 + tid];
        dns[tid] = d;
    }
    __syncthreads();
    int q0 = m * 64;
    for (int i = tid; i < 16384; i += 256) {
        int r = i >> 8, c = i & 255;
        float a = 0.f;
        for (int s = 0; s < cnt; s++) a += g_pacc[(size_t)(slot0 + s) * 16384 + i];
        int q = q0 + r;
        Out[((size_t)(b * Sq + q)) * 256 + c] = a / ((float)(q + 1) * dns[r]);
    }
}

// ---------------------------------------------------------------------------
extern "C" void kernel_launch(void* const* d_in, const int* in_sizes, int n_in,
                              void* d_out, int out_size) {
    const float* e  = (const float*)d_in[0];
    const float* p  = (const float*)d_in[1];
    const float* Wo = (const float*)d_in[2];
    float* out = (float*)d_out;

    cudaFuncSetAttribute(attn_mma_kernel, cudaFuncAttributeMaxDynamicSharedMemorySize, SM_TOTAL);
    cudaFuncSetAttribute(e2t_mma_kernel, cudaFuncAttributeMaxDynamicSharedMemorySize, EW_TOTAL);

    weff_kernel<<<Dd, Dd>>>(Wo);
    conv_kernel<<<(Bsz * (Sq + 1) * Dd) / 1024, 256>>>(p, 0);
    conv_kernel<<<(Bsz * Sq * Dd) / 1024, 256>>>(e, 1);
    e2t_mma_kernel<<<dim3(64, 4), 512, EW_TOTAL>>>();
    attn_mma_kernel<<<640, 512, SM_TOTAL>>>(out);
    reduce_kernel<<<192, 256>>>(out);
}